// round 11
// baseline (speedup 1.0000x reference)
#include <cuda_runtime.h>

#define N_ANCH 5000
#define N_CLS 80
#define WORDS 157
#define WSTRIDE 160
#define MAXB 300
#define SCORE_THR_F 0.05f
#define OUT_COLS 84
#define NBUCK 4096
#define KEYCAP 5120
#define CLS_T_STRIDE 5120
#define NTILES ((WORDS * (WORDS + 1)) / 2)
#define A_BLOCKS ((NTILES * 32 + 255) / 256)        // 1551
#define T_BLOCKS ((N_ANCH * N_CLS + 255) / 256)     // 1563
#define SCAN_T 256

__device__ unsigned int g_mask[N_ANCH * WSTRIDE];
__device__ unsigned int g_kept[N_CLS * WSTRIDE];
__device__ float        g_clsT[N_CLS * CLS_T_STRIDE];
__device__ unsigned int g_list[N_CLS * KEYCAP];
__device__ int          g_cnt[N_CLS];

// ---------------------------------------------------------------------------
// exact decision bit: fl(inter/uni) > 0.5; division-free except in a 1e-6
// relative band where exact __fdiv_rn decides. Identical op sequence in prep
// and scan => bit-identical results.
// ---------------------------------------------------------------------------
__device__ __forceinline__ bool iou_gt_half(const float4& bi, float ai,
                                            const float4& bj, float aj) {
    float iw = fmaxf(__fsub_rn(fminf(bi.z, bj.z), fmaxf(bi.x, bj.x)), 0.0f);
    float ih = fmaxf(__fsub_rn(fminf(bi.w, bj.w), fmaxf(bi.y, bj.y)), 0.0f);
    float inter = __fmul_rn(iw, ih);
    float uni   = __fsub_rn(__fadd_rn(ai, aj), inter);
    float diff  = __fmaf_rn(inter, 2.0f, -uni);
    bool pred = diff > 0.0f;
    if (fabsf(diff) <= __fmul_rn(uni, 1e-6f)) {
        float iou = __fdiv_rn(inter, fmaxf(uni, 1e-8f));
        pred = (iou > 0.5f);
    }
    return pred;
}

// ---------------------------------------------------------------------------
// 32x32 warp bit transpose
// ---------------------------------------------------------------------------
__device__ __forceinline__ unsigned bit_transpose32(unsigned x, int lane) {
    const unsigned lom[5] = {0x0000FFFFu, 0x00FF00FFu, 0x0F0F0F0Fu, 0x33333333u, 0x55555555u};
    const int      shs[5] = {16, 8, 4, 2, 1};
#pragma unroll
    for (int s = 0; s < 5; ++s) {
        unsigned y = __shfl_xor_sync(0xffffffffu, x, shs[s]);
        unsigned lo = lom[s];
        if ((lane & shs[s]) == 0) x = (x & lo)  | ((y & lo)  << shs[s]);
        else                      x = (x & ~lo) | ((y & ~lo) >> shs[s]);
    }
    return x;
}

// ---------------------------------------------------------------------------
// Kernel P (fused): blocks [0, A_BLOCKS) do IoU tiles; rest transpose cls.
// ---------------------------------------------------------------------------
__global__ void __launch_bounds__(256)
prep_kernel(const float4* __restrict__ boxes, const float* __restrict__ cls) {
    __shared__ float4 sbox[8][32];
    __shared__ float  sarea[8][32];

    if (blockIdx.x >= A_BLOCKS) {
        int t = (blockIdx.x - A_BLOCKS) * 256 + threadIdx.x;
        if (t < N_ANCH * N_CLS) {
            int i = t / N_CLS, c = t - i * N_CLS;
            g_clsT[c * CLS_T_STRIDE + i] = cls[t];
        }
        return;
    }

    const int gw   = (blockIdx.x * blockDim.x + threadIdx.x) >> 5;
    const int lane = threadIdx.x & 31;
    const int wib  = (threadIdx.x >> 5);
    if (gw >= NTILES) return;

    int J = (int)((sqrtf(8.0f * (float)gw + 1.0f) - 1.0f) * 0.5f);
    while ((J + 1) * (J + 2) / 2 <= gw) ++J;
    while (J * (J + 1) / 2 > gw) --J;
    const int I = gw - J * (J + 1) / 2;

    const int row = (I << 5) + lane;
    const float4 bi = __ldg(&boxes[min(row, N_ANCH - 1)]);
    const float  ai = __fmul_rn(__fsub_rn(bi.z, bi.x), __fsub_rn(bi.w, bi.y));

    const int colL = (J << 5) + lane;
    {
        float4 bc = __ldg(&boxes[min(colL, N_ANCH - 1)]);
        sbox[wib][lane]  = bc;
        sarea[wib][lane] = __fmul_rn(__fsub_rn(bc.z, bc.x), __fsub_rn(bc.w, bc.y));
    }
    __syncwarp(0xffffffffu);

    unsigned word = 0u;
#pragma unroll
    for (int j = 0; j < 32; ++j) {
        if (iou_gt_half(bi, ai, sbox[wib][j], sarea[wib][j]))
            word |= (1u << j);
    }

    const unsigned cmaskJ = (J == WORDS - 1) ? 0xFFu : 0xFFFFFFFFu;
    const unsigned cmaskI = (I == WORDS - 1) ? 0xFFu : 0xFFFFFFFFu;
    word &= cmaskJ;

    if (I == J) {
        word &= ~(1u << lane);
        if (row < N_ANCH) g_mask[row * WSTRIDE + J] = word;
    } else {
        unsigned t = bit_transpose32(word, lane) & cmaskI;
        g_mask[row * WSTRIDE + J] = word;
        if (colL < N_ANCH) g_mask[colL * WSTRIDE + I] = t;
    }
}

// ---------------------------------------------------------------------------
// Kernel B1: per-class exact stable descending sort -> g_list / g_cnt
// ---------------------------------------------------------------------------
#define BT 1024

__global__ void __launch_bounds__(BT, 1)
sort_class_kernel() {
    extern __shared__ unsigned char sh_raw[];
    unsigned long long* keys = (unsigned long long*)sh_raw;
    unsigned int* hist   = (unsigned int*)(keys + KEYCAP);
    unsigned int* starts = hist + NBUCK;
    __shared__ unsigned int wsum[32];
    __shared__ int s_cnt;

    const int c = blockIdx.x;
    const int tid = threadIdx.x;
    const int lane = tid & 31;
    const int wid = tid >> 5;
    const float* col = &g_clsT[c * CLS_T_STRIDE];

    for (int b = tid; b < NBUCK; b += BT) hist[b] = 0u;
    __syncthreads();

    for (int i = tid; i < N_ANCH; i += BT) {
        float s = col[i];
        if (s > SCORE_THR_F) {
            int b = min((int)__fmul_rn(s, 4096.0f), NBUCK - 1);
            atomicAdd(&hist[NBUCK - 1 - b], 1u);
        }
    }
    __syncthreads();

    {
        unsigned h0 = hist[tid * 4 + 0], h1 = hist[tid * 4 + 1];
        unsigned h2 = hist[tid * 4 + 2], h3 = hist[tid * 4 + 3];
        unsigned tsum = h0 + h1 + h2 + h3;
        unsigned x = tsum;
#pragma unroll
        for (int o = 1; o < 32; o <<= 1) {
            unsigned y = __shfl_up_sync(0xffffffffu, x, o);
            if (lane >= o) x += y;
        }
        if (lane == 31) wsum[wid] = x;
        __syncthreads();
        if (wid == 0) {
            unsigned v = wsum[lane], xx = v;
#pragma unroll
            for (int o = 1; o < 32; o <<= 1) {
                unsigned y = __shfl_up_sync(0xffffffffu, xx, o);
                if (lane >= o) xx += y;
            }
            wsum[lane] = xx;
            if (lane == 31) s_cnt = (int)xx;
        }
        __syncthreads();
        unsigned te = ((wid > 0) ? wsum[wid - 1] : 0u) + (x - tsum);
        hist[tid * 4 + 0] = te;                  starts[tid * 4 + 0] = te;
        hist[tid * 4 + 1] = te + h0;             starts[tid * 4 + 1] = te + h0;
        hist[tid * 4 + 2] = te + h0 + h1;        starts[tid * 4 + 2] = te + h0 + h1;
        hist[tid * 4 + 3] = te + h0 + h1 + h2;   starts[tid * 4 + 3] = te + h0 + h1 + h2;
    }
    __syncthreads();
    const int cnt = s_cnt;

    for (int i = tid; i < N_ANCH; i += BT) {
        float s = col[i];
        if (s > SCORE_THR_F) {
            int b = min((int)__fmul_rn(s, 4096.0f), NBUCK - 1);
            unsigned pos = atomicAdd(&hist[NBUCK - 1 - b], 1u);
            keys[pos] = ((unsigned long long)__float_as_uint(s) << 32) |
                        (unsigned long long)(0xFFFFFFFFu - (unsigned)i);
        }
    }
    __syncthreads();

    for (int b = tid; b < NBUCK; b += BT) {
        int s0 = (int)starts[b], e0 = (int)hist[b];
        for (int i = s0 + 1; i < e0; ++i) {
            unsigned long long kv = keys[i];
            int j = i - 1;
            while (j >= s0 && keys[j] < kv) { keys[j + 1] = keys[j]; --j; }
            keys[j + 1] = kv;
        }
    }
    __syncthreads();

    if (tid == 0) g_cnt[c] = cnt;
    for (int p = tid; p < cnt; p += BT)
        g_list[c * KEYCAP + p] = 0xFFFFFFFFu - (unsigned)keys[p];
}

// ---------------------------------------------------------------------------
// Kernel B2: greedy scan — R9 skeleton with intra-batch overlap:
// warps 1-7 stage the 32 mask rows (coalesced, 5 rows/warp) WHILE warp 0
// recomputes the 32x32 pairwise bits from boxes (bit-identical to g_mask)
// and serially resolves. 3 block barriers per batch.
// ---------------------------------------------------------------------------
__global__ void __launch_bounds__(SCAN_T, 1)
nms_scan_kernel(const float4* __restrict__ boxes) {
    __shared__ unsigned slist[KEYCAP];          // 20480 B
    __shared__ unsigned srow[35][WSTRIDE];      // staged rows (warps 1-7 x 5)
    __shared__ unsigned supp[WSTRIDE];
    __shared__ unsigned keptb[WSTRIDE];
    __shared__ unsigned s_m[8];
    __shared__ float4   sbox[32];
    __shared__ float    sarea[32];
    __shared__ unsigned sbits[32];
    __shared__ unsigned s_kb;

    const int c = blockIdx.x;
    const int tid = threadIdx.x;
    const int lane = tid & 31;
    const int w = tid >> 5;
    const int cnt = g_cnt[c];

    for (int i = tid; i < WSTRIDE; i += SCAN_T) { supp[i] = 0u; keptb[i] = 0u; }
    for (int i = tid; i < cnt; i += SCAN_T) slist[i] = __ldg(&g_list[c * KEYCAP + i]);
    __syncthreads();

    int count = 0;
    int cur = 0;
    while (cur < cnt && count < MAXB) {
        // 1) alive ballot over 256-wide window (supp is CURRENT — no staleness)
        int pos = cur + tid;
        bool ok = (pos < cnt);
        unsigned ca = ok ? slist[pos] : 0u;
        bool alive = ok && !((supp[ca >> 5] >> (ca & 31)) & 1u);
        unsigned bm = __ballot_sync(0xffffffffu, alive);
        if (lane == 0) s_m[w] = bm;
        __syncthreads();                                    // B1

        unsigned mwords[8];
        int tot = 0;
#pragma unroll
        for (int q = 0; q < 8; ++q) { mwords[q] = s_m[q]; tot += __popc(mwords[q]); }
        int nf = min(tot, 32);
        if (nf == 0) { cur += SCAN_T; __syncthreads(); continue; }

        // 2) redundant per-warp rank-select: lane L holds candidate L
        int rem = lane;
        int psel = -1;
#pragma unroll
        for (int q = 0; q < 8; ++q) {
            int cq = __popc(mwords[q]);
            if (psel < 0) {
                if (rem < cq) psel = (q << 5) + (int)__fns(mwords[q], 0, rem + 1);
                else rem -= cq;
            }
        }
        unsigned a_l = (lane < nf) ? slist[cur + psel] : 0u;
        int plast = __shfl_sync(0xffffffffu, psel, nf - 1);
        int adv = (tot <= 32) ? SCAN_T : (plast + 1);

        unsigned r[5][5];
        if (w == 0) {
            // --- pairwise from boxes + serial resolve (overlaps row staging) ---
            if (lane < nf) {
                float4 b = __ldg(&boxes[a_l]);
                sbox[lane]  = b;
                sarea[lane] = __fmul_rn(__fsub_rn(b.z, b.x), __fsub_rn(b.w, b.y));
            }
            __syncwarp(0xffffffffu);
            unsigned bitsk = 0u;
            if (lane < nf) {
                float4 bk = sbox[lane];
                float  ak = sarea[lane];
                for (int m = 0; m < nf; ++m) {
                    if (m != lane && iou_gt_half(bk, ak, sbox[m], sarea[m]))
                        bitsk |= (1u << m);
                }
            }
            sbits[lane] = bitsk;
            __syncwarp(0xffffffffu);
            if (lane == 0) {
                unsigned kb = 0u;
                unsigned pend = (nf >= 32) ? 0xffffffffu : ((1u << nf) - 1u);
                int cl = count;
                while (pend && cl < MAXB) {
                    int f = __ffs(pend) - 1;
                    kb |= (1u << f); ++cl;
                    pend &= ~(1u << f);
                    pend &= ~sbits[f];       // symmetric matrix
                }
                s_kb = kb;
            }
            __syncwarp(0xffffffffu);
            unsigned kb0 = s_kb;
            if (lane < nf && ((kb0 >> lane) & 1u))
                atomicOr(&keptb[a_l >> 5], 1u << (a_l & 31u));
        } else {
            // --- row staging: warp w handles rows (w-1)*5 .. (w-1)*5+4 ---
#pragma unroll
            for (int j = 0; j < 5; ++j) {
                int k = (w - 1) * 5 + j;
                unsigned ak = __shfl_sync(0xffffffffu, a_l, k & 31);
                if (k < nf) {
#pragma unroll
                    for (int u = 0; u < 5; ++u) {
                        int wd = lane + (u << 5);
                        unsigned v = (wd < WORDS) ? __ldg(&g_mask[(size_t)ak * WSTRIDE + wd]) : 0u;
                        r[j][u] = v;
                        srow[k][wd] = v;
                    }
                } else {
#pragma unroll
                    for (int u = 0; u < 5; ++u) r[j][u] = 0u;
                }
            }
        }
        __syncthreads();                                    // B2: rows + s_kb ready

        unsigned kb = s_kb;
        count += __popc(kb);

        // 3) OR kept rows into supp (warps 1-7, from registers)
        if (w > 0) {
            unsigned comb[5] = {0u, 0u, 0u, 0u, 0u};
#pragma unroll
            for (int j = 0; j < 5; ++j) {
                int k = (w - 1) * 5 + j;
                if (k < nf && ((kb >> k) & 1u)) {
#pragma unroll
                    for (int u = 0; u < 5; ++u) comb[u] |= r[j][u];
                }
            }
#pragma unroll
            for (int u = 0; u < 5; ++u) {
                int wd = lane + (u << 5);
                if (wd < WORDS && comb[u]) atomicOr(&supp[wd], comb[u]);
            }
        }
        __syncthreads();                                    // B3

        cur += adv;
    }
    __syncthreads();

    for (int i = tid; i < WSTRIDE; i += SCAN_T)
        g_kept[c * WSTRIDE + i] = keptb[i];
}

// ---------------------------------------------------------------------------
// Kernel C: vectorized assemble — one float4 (21 per anchor) per thread
// ---------------------------------------------------------------------------
__global__ void __launch_bounds__(256)
assemble4_kernel(const float4* __restrict__ boxes4,
                 const float4* __restrict__ cls4,
                 float4* __restrict__ out4) {
    int t = blockIdx.x * blockDim.x + threadIdx.x;
    if (t >= N_ANCH * 21) return;
    int i = t / 21;
    int q = t - i * 21;
    float4 v;
    if (q == 0) {
        v = __ldg(&boxes4[i]);
    } else {
        int c0 = (q - 1) * 4;
        v = __ldg(&cls4[(i * N_CLS + c0) >> 2]);
        unsigned wi = (unsigned)i >> 5, bi = (unsigned)i & 31u;
        if (!((g_kept[(c0 + 0) * WSTRIDE + wi] >> bi) & 1u)) v.x = 0.0f;
        if (!((g_kept[(c0 + 1) * WSTRIDE + wi] >> bi) & 1u)) v.y = 0.0f;
        if (!((g_kept[(c0 + 2) * WSTRIDE + wi] >> bi) & 1u)) v.z = 0.0f;
        if (!((g_kept[(c0 + 3) * WSTRIDE + wi] >> bi) & 1u)) v.w = 0.0f;
    }
    out4[t] = v;
}

// ---------------------------------------------------------------------------
extern "C" void kernel_launch(void* const* d_in, const int* in_sizes, int n_in,
                              void* d_out, int out_size) {
    const float* boxes = (const float*)d_in[0];
    const float* cls   = (const float*)d_in[1];
    float* out = (float*)d_out;

    {   // P: fused IoU tiles + transpose
        prep_kernel<<<A_BLOCKS + T_BLOCKS, 256>>>((const float4*)boxes, cls);
    }
    {   // B1: per-class sort
        size_t smem = (size_t)KEYCAP * 8 + (size_t)NBUCK * 4 * 2;
        cudaFuncSetAttribute(sort_class_kernel,
                             cudaFuncAttributeMaxDynamicSharedMemorySize,
                             (int)smem);
        sort_class_kernel<<<N_CLS, BT, smem>>>();
    }
    {   // B2: overlapped greedy scan
        nms_scan_kernel<<<N_CLS, SCAN_T>>>((const float4*)boxes);
    }
    {   // C: vectorized assemble
        int total = N_ANCH * 21;
        assemble4_kernel<<<(total + 255) / 256, 256>>>(
            (const float4*)boxes, (const float4*)cls, (float4*)out);
    }
}

// round 12
// speedup vs baseline: 1.3615x; 1.3615x over previous
#include <cuda_runtime.h>

#define N_ANCH 5000
#define N_CLS 80
#define WORDS 157
#define WSTRIDE 160
#define MAXB 300
#define SCORE_THR_F 0.05f
#define NBUCK 4096
#define KEYCAP 5120
#define CLS_T_STRIDE 5120
#define NTILES ((WORDS * (WORDS + 1)) / 2)
#define A_BLOCKS ((NTILES * 32 + 255) / 256)        // 1551
#define T_BLOCKS ((N_ANCH * N_CLS + 255) / 256)     // 1563
#define SCAN_T 256
#define BT 1024

__device__ unsigned int g_mask[N_ANCH * WSTRIDE];
__device__ unsigned int g_kept[N_CLS * WSTRIDE];
__device__ float        g_clsT[N_CLS * CLS_T_STRIDE];

// ---------------------------------------------------------------------------
// 32x32 warp bit transpose
// ---------------------------------------------------------------------------
__device__ __forceinline__ unsigned bit_transpose32(unsigned x, int lane) {
    const unsigned lom[5] = {0x0000FFFFu, 0x00FF00FFu, 0x0F0F0F0Fu, 0x33333333u, 0x55555555u};
    const int      shs[5] = {16, 8, 4, 2, 1};
#pragma unroll
    for (int s = 0; s < 5; ++s) {
        unsigned y = __shfl_xor_sync(0xffffffffu, x, shs[s]);
        unsigned lo = lom[s];
        if ((lane & shs[s]) == 0) x = (x & lo)  | ((y & lo)  << shs[s]);
        else                      x = (x & ~lo) | ((y & ~lo) >> shs[s]);
    }
    return x;
}

// ---------------------------------------------------------------------------
// Kernel P (fused): blocks [0, A_BLOCKS) do IoU tiles; rest transpose cls.
// ---------------------------------------------------------------------------
__global__ void __launch_bounds__(256)
prep_kernel(const float4* __restrict__ boxes, const float* __restrict__ cls) {
    __shared__ float4 sbox[8][32];
    __shared__ float  sarea[8][32];

    if (blockIdx.x >= A_BLOCKS) {
        int t = (blockIdx.x - A_BLOCKS) * 256 + threadIdx.x;
        if (t < N_ANCH * N_CLS) {
            int i = t / N_CLS, c = t - i * N_CLS;
            g_clsT[c * CLS_T_STRIDE + i] = cls[t];
        }
        return;
    }

    const int gw   = (blockIdx.x * blockDim.x + threadIdx.x) >> 5;
    const int lane = threadIdx.x & 31;
    const int wib  = (threadIdx.x >> 5);
    if (gw >= NTILES) return;

    int J = (int)((sqrtf(8.0f * (float)gw + 1.0f) - 1.0f) * 0.5f);
    while ((J + 1) * (J + 2) / 2 <= gw) ++J;
    while (J * (J + 1) / 2 > gw) --J;
    const int I = gw - J * (J + 1) / 2;

    const int row = (I << 5) + lane;
    const float4 bi = __ldg(&boxes[min(row, N_ANCH - 1)]);
    const float  ai = __fmul_rn(__fsub_rn(bi.z, bi.x), __fsub_rn(bi.w, bi.y));

    const int colL = (J << 5) + lane;
    {
        float4 bc = __ldg(&boxes[min(colL, N_ANCH - 1)]);
        sbox[wib][lane]  = bc;
        sarea[wib][lane] = __fmul_rn(__fsub_rn(bc.z, bc.x), __fsub_rn(bc.w, bc.y));
    }
    __syncwarp(0xffffffffu);

    unsigned word = 0u, fix = 0u;
#pragma unroll
    for (int j = 0; j < 32; ++j) {
        float4 bj = sbox[wib][j];
        float  aj = sarea[wib][j];
        float iw = fmaxf(__fsub_rn(fminf(bi.z, bj.z), fmaxf(bi.x, bj.x)), 0.0f);
        float ih = fmaxf(__fsub_rn(fminf(bi.w, bj.w), fmaxf(bi.y, bj.y)), 0.0f);
        float inter = __fmul_rn(iw, ih);
        float uni   = __fsub_rn(__fadd_rn(ai, aj), inter);
        float diff  = __fmaf_rn(inter, 2.0f, -uni);
        if (diff > 0.0f)                          word |= (1u << j);
        if (fabsf(diff) <= __fmul_rn(uni, 1e-6f)) fix  |= (1u << j);
    }

    if (__any_sync(0xffffffffu, fix != 0u)) {
        while (fix) {
            int j = __ffs(fix) - 1; fix &= fix - 1u;
            float4 bj = sbox[wib][j];
            float  aj = sarea[wib][j];
            float iw = fmaxf(__fsub_rn(fminf(bi.z, bj.z), fmaxf(bi.x, bj.x)), 0.0f);
            float ih = fmaxf(__fsub_rn(fminf(bi.w, bj.w), fmaxf(bi.y, bj.y)), 0.0f);
            float inter = __fmul_rn(iw, ih);
            float uni   = __fsub_rn(__fadd_rn(ai, aj), inter);
            float iou   = __fdiv_rn(inter, fmaxf(uni, 1e-8f));
            if (iou > 0.5f) word |=  (1u << j);
            else            word &= ~(1u << j);
        }
    }

    const unsigned cmaskJ = (J == WORDS - 1) ? 0xFFu : 0xFFFFFFFFu;
    const unsigned cmaskI = (I == WORDS - 1) ? 0xFFu : 0xFFFFFFFFu;
    word &= cmaskJ;

    if (I == J) {
        word &= ~(1u << lane);
        if (row < N_ANCH) g_mask[row * WSTRIDE + J] = word;
    } else {
        unsigned t = bit_transpose32(word, lane) & cmaskI;
        g_mask[row * WSTRIDE + J] = word;
        if (colL < N_ANCH) g_mask[colL * WSTRIDE + I] = t;
    }
}

// ---------------------------------------------------------------------------
// Kernel B (fused sort+scan): one block (1024 thr) per class.
// Phase 1: counting sort + per-bucket insertion sort (R5 B1, verbatim).
// Phase 2: slist built in smem (no global round-trip), then the VERBATIM
// R5 champion scan with the window gated to tid<256; warps 8-31 no-op
// through the k<nf guards and just join barriers.
// Shared memory is time-sliced: keys region -> srow, hist/starts -> slist.
// ---------------------------------------------------------------------------
__global__ void __launch_bounds__(BT, 1)
nms_class_kernel() {
    extern __shared__ unsigned char sh_raw[];
    unsigned long long* keys = (unsigned long long*)sh_raw;          // [0, 40960)
    unsigned int* hist   = (unsigned int*)(sh_raw + 40960);          // 16384 B
    unsigned int* starts = hist + NBUCK;                             // 16384 B
    // phase-2 aliases
    unsigned (*srow)[WSTRIDE] = (unsigned (*)[WSTRIDE])sh_raw;       // 20480 B over keys
    unsigned* slist = (unsigned*)(sh_raw + 40960);                   // 20480 B over hist+starts

    __shared__ unsigned supp[WSTRIDE];
    __shared__ unsigned keptb[WSTRIDE];
    __shared__ unsigned s_m[8];
    __shared__ unsigned sbits[32];
    __shared__ unsigned s_kb;
    __shared__ unsigned wsum[32];
    __shared__ int s_cnt;

    const int c = blockIdx.x;
    const int tid = threadIdx.x;
    const int lane = tid & 31;
    const int w = tid >> 5;
    const float* col = &g_clsT[c * CLS_T_STRIDE];

    // ---------------- Phase 1: sort ----------------
    for (int b = tid; b < NBUCK; b += BT) hist[b] = 0u;
    for (int i = tid; i < WSTRIDE; i += BT) { supp[i] = 0u; keptb[i] = 0u; }
    __syncthreads();

    for (int i = tid; i < N_ANCH; i += BT) {
        float s = col[i];
        if (s > SCORE_THR_F) {
            int b = min((int)__fmul_rn(s, 4096.0f), NBUCK - 1);
            atomicAdd(&hist[NBUCK - 1 - b], 1u);
        }
    }
    __syncthreads();

    {
        unsigned h0 = hist[tid * 4 + 0], h1 = hist[tid * 4 + 1];
        unsigned h2 = hist[tid * 4 + 2], h3 = hist[tid * 4 + 3];
        unsigned tsum = h0 + h1 + h2 + h3;
        unsigned x = tsum;
#pragma unroll
        for (int o = 1; o < 32; o <<= 1) {
            unsigned y = __shfl_up_sync(0xffffffffu, x, o);
            if (lane >= o) x += y;
        }
        if (lane == 31) wsum[w] = x;
        __syncthreads();
        if (w == 0) {
            unsigned v = wsum[lane], xx = v;
#pragma unroll
            for (int o = 1; o < 32; o <<= 1) {
                unsigned y = __shfl_up_sync(0xffffffffu, xx, o);
                if (lane >= o) xx += y;
            }
            wsum[lane] = xx;
            if (lane == 31) s_cnt = (int)xx;
        }
        __syncthreads();
        unsigned te = ((w > 0) ? wsum[w - 1] : 0u) + (x - tsum);
        hist[tid * 4 + 0] = te;                  starts[tid * 4 + 0] = te;
        hist[tid * 4 + 1] = te + h0;             starts[tid * 4 + 1] = te + h0;
        hist[tid * 4 + 2] = te + h0 + h1;        starts[tid * 4 + 2] = te + h0 + h1;
        hist[tid * 4 + 3] = te + h0 + h1 + h2;   starts[tid * 4 + 3] = te + h0 + h1 + h2;
    }
    __syncthreads();
    const int cnt = s_cnt;

    for (int i = tid; i < N_ANCH; i += BT) {
        float s = col[i];
        if (s > SCORE_THR_F) {
            int b = min((int)__fmul_rn(s, 4096.0f), NBUCK - 1);
            unsigned pos = atomicAdd(&hist[NBUCK - 1 - b], 1u);
            keys[pos] = ((unsigned long long)__float_as_uint(s) << 32) |
                        (unsigned long long)(0xFFFFFFFFu - (unsigned)i);
        }
    }
    __syncthreads();

    for (int b = tid; b < NBUCK; b += BT) {
        int s0 = (int)starts[b], e0 = (int)hist[b];
        for (int i = s0 + 1; i < e0; ++i) {
            unsigned long long kv = keys[i];
            int j = i - 1;
            while (j >= s0 && keys[j] < kv) { keys[j + 1] = keys[j]; --j; }
            keys[j + 1] = kv;
        }
    }
    __syncthreads();

    // build slist over the hist/starts region (keys intact until read)
    for (int p = tid; p < cnt; p += BT)
        slist[p] = 0xFFFFFFFFu - (unsigned)keys[p];
    __syncthreads();
    // keys region now free -> becomes srow

    // ---------------- Phase 2: scan (verbatim R5, window gated to tid<256) --
    int count = 0;
    int cur = 0;
    while (cur < cnt && count < MAXB) {
        // 1) alive check for 256 positions
        int pos = cur + tid;
        bool ok = (tid < SCAN_T) && (pos < cnt);
        unsigned ca = ok ? slist[pos] : 0u;
        bool alive = ok && !((supp[ca >> 5] >> (ca & 31)) & 1u);
        unsigned bm = __ballot_sync(0xffffffffu, alive);
        if (lane == 0 && w < 8) s_m[w] = bm;
        __syncthreads();

        unsigned mwords[8];
        int tot = 0;
#pragma unroll
        for (int q = 0; q < 8; ++q) { mwords[q] = s_m[q]; tot += __popc(mwords[q]); }
        int nf = min(tot, 32);

        if (nf == 0) { cur += SCAN_T; __syncthreads(); continue; }

        // 2) per-lane rank-select (every warp, redundant, R5-style)
        int rem = lane;
        int psel = -1;
#pragma unroll
        for (int q = 0; q < 8; ++q) {
            int cq = __popc(mwords[q]);
            if (psel < 0) {
                if (rem < cq) psel = (q << 5) + (int)__fns(mwords[q], 0, rem + 1);
                else rem -= cq;
            }
        }
        unsigned a_l = (lane < nf) ? slist[cur + psel] : 0u;

        // 3) row loads: warp w loads rows k = 4w..4w+3 (k<nf false for w>=8)
        unsigned r[4][5];
#pragma unroll
        for (int j = 0; j < 4; ++j) {
            int k = (w << 2) + j;
            unsigned ak = __shfl_sync(0xffffffffu, a_l, k & 31);
            if (k < nf) {
#pragma unroll
                for (int u = 0; u < 5; ++u) {
                    int wd = lane + (u << 5);
                    unsigned v = (wd < WORDS) ? __ldg(&g_mask[ak * WSTRIDE + wd]) : 0u;
                    r[j][u] = v;
                    srow[k][wd] = v;
                }
            } else {
#pragma unroll
                for (int u = 0; u < 5; ++u) r[j][u] = 0u;
            }
        }
        __syncthreads();

        // 4) pairwise gather + serial greedy resolve (warp 0)
        if (w == 0) {
            unsigned bitsk = 0u;
            if (lane < nf) {
                unsigned aw = a_l >> 5, ab = a_l & 31u;
#pragma unroll
                for (int m = 0; m < 32; ++m)
                    bitsk |= ((srow[m][aw] >> ab) & 1u) << m;
            }
            sbits[lane] = bitsk;
            __syncwarp(0xffffffffu);
            if (lane == 0) {
                unsigned kb = 0u;
                int cl = count;
                for (int k = 0; k < nf; ++k) {
                    unsigned bk = sbits[k];
                    if (!(bk & kb) && cl < MAXB) { kb |= (1u << k); ++cl; }
                }
                s_kb = kb;
            }
            __syncwarp(0xffffffffu);
            unsigned kb0 = s_kb;
            if (lane < nf && ((kb0 >> lane) & 1u))
                atomicOr(&keptb[a_l >> 5], 1u << (a_l & 31u));
        }
        __syncthreads();

        unsigned kb = s_kb;
        count += __popc(kb);

        // 5) OR kept rows into supp (warps 0-7, from registers)
        unsigned comb[5] = {0u, 0u, 0u, 0u, 0u};
#pragma unroll
        for (int j = 0; j < 4; ++j) {
            int k = (w << 2) + j;
            if (k < nf && ((kb >> k) & 1u)) {
#pragma unroll
                for (int u = 0; u < 5; ++u) comb[u] |= r[j][u];
            }
        }
#pragma unroll
        for (int u = 0; u < 5; ++u) {
            int wd = lane + (u << 5);
            if (wd < WORDS && comb[u]) atomicOr(&supp[wd], comb[u]);
        }
        __syncthreads();

        // 6) advance past the last selected candidate
        int plast = __shfl_sync(0xffffffffu, psel, nf - 1);
        cur += (tot <= 32) ? SCAN_T : (plast + 1);
    }
    __syncthreads();

    for (int i = tid; i < WSTRIDE; i += BT)
        g_kept[c * WSTRIDE + i] = keptb[i];
}

// ---------------------------------------------------------------------------
// Kernel C: vectorized assemble — one float4 (21 per anchor) per thread
// ---------------------------------------------------------------------------
__global__ void __launch_bounds__(256)
assemble4_kernel(const float4* __restrict__ boxes4,
                 const float4* __restrict__ cls4,
                 float4* __restrict__ out4) {
    int t = blockIdx.x * blockDim.x + threadIdx.x;
    if (t >= N_ANCH * 21) return;
    int i = t / 21;
    int q = t - i * 21;
    float4 v;
    if (q == 0) {
        v = __ldg(&boxes4[i]);
    } else {
        int c0 = (q - 1) * 4;
        v = __ldg(&cls4[(i * N_CLS + c0) >> 2]);
        unsigned wi = (unsigned)i >> 5, bi = (unsigned)i & 31u;
        if (!((g_kept[(c0 + 0) * WSTRIDE + wi] >> bi) & 1u)) v.x = 0.0f;
        if (!((g_kept[(c0 + 1) * WSTRIDE + wi] >> bi) & 1u)) v.y = 0.0f;
        if (!((g_kept[(c0 + 2) * WSTRIDE + wi] >> bi) & 1u)) v.z = 0.0f;
        if (!((g_kept[(c0 + 3) * WSTRIDE + wi] >> bi) & 1u)) v.w = 0.0f;
    }
    out4[t] = v;
}

// ---------------------------------------------------------------------------
extern "C" void kernel_launch(void* const* d_in, const int* in_sizes, int n_in,
                              void* d_out, int out_size) {
    const float* boxes = (const float*)d_in[0];
    const float* cls   = (const float*)d_in[1];
    float* out = (float*)d_out;

    {   // P: fused IoU tiles + transpose
        prep_kernel<<<A_BLOCKS + T_BLOCKS, 256>>>((const float4*)boxes, cls);
    }
    {   // B: fused per-class sort + scan
        size_t smem = (size_t)KEYCAP * 8 + (size_t)NBUCK * 4 * 2;  // 73728
        cudaFuncSetAttribute(nms_class_kernel,
                             cudaFuncAttributeMaxDynamicSharedMemorySize,
                             (int)smem);
        nms_class_kernel<<<N_CLS, BT, smem>>>();
    }
    {   // C: vectorized assemble
        int total = N_ANCH * 21;
        assemble4_kernel<<<(total + 255) / 256, 256>>>(
            (const float4*)boxes, (const float4*)cls, (float4*)out);
    }
}

// round 13
// speedup vs baseline: 1.4837x; 1.0898x over previous
#include <cuda_runtime.h>

#define N_ANCH 5000
#define N_CLS 80
#define WORDS 157
#define WSTRIDE 160
#define MAXB 300
#define SCORE_THR_F 0.05f
#define NBUCK 4096
#define KEYCAP 5120
#define CLS_T_STRIDE 5120
#define NTILES ((WORDS * (WORDS + 1)) / 2)
#define A_BLOCKS ((NTILES * 32 + 255) / 256)        // 1551
#define T_BLOCKS ((N_ANCH * N_CLS + 255) / 256)     // 1563
#define SCAN_T 256
#define BT 1024

__device__ unsigned int g_mask[N_ANCH * WSTRIDE];
__device__ unsigned int g_kept[N_CLS * WSTRIDE];
__device__ float        g_clsT[N_CLS * CLS_T_STRIDE];
__device__ unsigned int g_list[N_CLS * KEYCAP];
__device__ int          g_cnt[N_CLS];

// ---------------------------------------------------------------------------
// 32x32 warp bit transpose
// ---------------------------------------------------------------------------
__device__ __forceinline__ unsigned bit_transpose32(unsigned x, int lane) {
    const unsigned lom[5] = {0x0000FFFFu, 0x00FF00FFu, 0x0F0F0F0Fu, 0x33333333u, 0x55555555u};
    const int      shs[5] = {16, 8, 4, 2, 1};
#pragma unroll
    for (int s = 0; s < 5; ++s) {
        unsigned y = __shfl_xor_sync(0xffffffffu, x, shs[s]);
        unsigned lo = lom[s];
        if ((lane & shs[s]) == 0) x = (x & lo)  | ((y & lo)  << shs[s]);
        else                      x = (x & ~lo) | ((y & ~lo) >> shs[s]);
    }
    return x;
}

// ---------------------------------------------------------------------------
// Kernel P (fused): blocks [0, A_BLOCKS) do IoU tiles; rest transpose cls.
// ---------------------------------------------------------------------------
__global__ void __launch_bounds__(256)
prep_kernel(const float4* __restrict__ boxes, const float* __restrict__ cls) {
    __shared__ float4 sbox[8][32];
    __shared__ float  sarea[8][32];

    if (blockIdx.x >= A_BLOCKS) {
        int t = (blockIdx.x - A_BLOCKS) * 256 + threadIdx.x;
        if (t < N_ANCH * N_CLS) {
            int i = t / N_CLS, c = t - i * N_CLS;
            g_clsT[c * CLS_T_STRIDE + i] = cls[t];
        }
        return;
    }

    const int gw   = (blockIdx.x * blockDim.x + threadIdx.x) >> 5;
    const int lane = threadIdx.x & 31;
    const int wib  = (threadIdx.x >> 5);
    if (gw >= NTILES) return;

    int J = (int)((sqrtf(8.0f * (float)gw + 1.0f) - 1.0f) * 0.5f);
    while ((J + 1) * (J + 2) / 2 <= gw) ++J;
    while (J * (J + 1) / 2 > gw) --J;
    const int I = gw - J * (J + 1) / 2;

    const int row = (I << 5) + lane;
    const float4 bi = __ldg(&boxes[min(row, N_ANCH - 1)]);
    const float  ai = __fmul_rn(__fsub_rn(bi.z, bi.x), __fsub_rn(bi.w, bi.y));

    const int colL = (J << 5) + lane;
    {
        float4 bc = __ldg(&boxes[min(colL, N_ANCH - 1)]);
        sbox[wib][lane]  = bc;
        sarea[wib][lane] = __fmul_rn(__fsub_rn(bc.z, bc.x), __fsub_rn(bc.w, bc.y));
    }
    __syncwarp(0xffffffffu);

    unsigned word = 0u, fix = 0u;
#pragma unroll
    for (int j = 0; j < 32; ++j) {
        float4 bj = sbox[wib][j];
        float  aj = sarea[wib][j];
        float iw = fmaxf(__fsub_rn(fminf(bi.z, bj.z), fmaxf(bi.x, bj.x)), 0.0f);
        float ih = fmaxf(__fsub_rn(fminf(bi.w, bj.w), fmaxf(bi.y, bj.y)), 0.0f);
        float inter = __fmul_rn(iw, ih);
        float uni   = __fsub_rn(__fadd_rn(ai, aj), inter);
        float diff  = __fmaf_rn(inter, 2.0f, -uni);
        if (diff > 0.0f)                          word |= (1u << j);
        if (fabsf(diff) <= __fmul_rn(uni, 1e-6f)) fix  |= (1u << j);
    }

    if (__any_sync(0xffffffffu, fix != 0u)) {
        while (fix) {
            int j = __ffs(fix) - 1; fix &= fix - 1u;
            float4 bj = sbox[wib][j];
            float  aj = sarea[wib][j];
            float iw = fmaxf(__fsub_rn(fminf(bi.z, bj.z), fmaxf(bi.x, bj.x)), 0.0f);
            float ih = fmaxf(__fsub_rn(fminf(bi.w, bj.w), fmaxf(bi.y, bj.y)), 0.0f);
            float inter = __fmul_rn(iw, ih);
            float uni   = __fsub_rn(__fadd_rn(ai, aj), inter);
            float iou   = __fdiv_rn(inter, fmaxf(uni, 1e-8f));
            if (iou > 0.5f) word |=  (1u << j);
            else            word &= ~(1u << j);
        }
    }

    const unsigned cmaskJ = (J == WORDS - 1) ? 0xFFu : 0xFFFFFFFFu;
    const unsigned cmaskI = (I == WORDS - 1) ? 0xFFu : 0xFFFFFFFFu;
    word &= cmaskJ;

    if (I == J) {
        word &= ~(1u << lane);
        if (row < N_ANCH) g_mask[row * WSTRIDE + J] = word;
    } else {
        unsigned t = bit_transpose32(word, lane) & cmaskI;
        g_mask[row * WSTRIDE + J] = word;
        if (colL < N_ANCH) g_mask[colL * WSTRIDE + I] = t;
    }
}

// ---------------------------------------------------------------------------
// Kernel B1: per-class exact stable descending sort -> g_list / g_cnt (R9)
// ---------------------------------------------------------------------------
__global__ void __launch_bounds__(BT, 1)
sort_class_kernel() {
    extern __shared__ unsigned char sh_raw[];
    unsigned long long* keys = (unsigned long long*)sh_raw;
    unsigned int* hist   = (unsigned int*)(keys + KEYCAP);
    unsigned int* starts = hist + NBUCK;
    __shared__ unsigned int wsum[32];
    __shared__ int s_cnt;

    const int c = blockIdx.x;
    const int tid = threadIdx.x;
    const int lane = tid & 31;
    const int wid = tid >> 5;
    const float* col = &g_clsT[c * CLS_T_STRIDE];

    for (int b = tid; b < NBUCK; b += BT) hist[b] = 0u;
    __syncthreads();

    for (int i = tid; i < N_ANCH; i += BT) {
        float s = col[i];
        if (s > SCORE_THR_F) {
            int b = min((int)__fmul_rn(s, 4096.0f), NBUCK - 1);
            atomicAdd(&hist[NBUCK - 1 - b], 1u);
        }
    }
    __syncthreads();

    {
        unsigned h0 = hist[tid * 4 + 0], h1 = hist[tid * 4 + 1];
        unsigned h2 = hist[tid * 4 + 2], h3 = hist[tid * 4 + 3];
        unsigned tsum = h0 + h1 + h2 + h3;
        unsigned x = tsum;
#pragma unroll
        for (int o = 1; o < 32; o <<= 1) {
            unsigned y = __shfl_up_sync(0xffffffffu, x, o);
            if (lane >= o) x += y;
        }
        if (lane == 31) wsum[wid] = x;
        __syncthreads();
        if (wid == 0) {
            unsigned v = wsum[lane], xx = v;
#pragma unroll
            for (int o = 1; o < 32; o <<= 1) {
                unsigned y = __shfl_up_sync(0xffffffffu, xx, o);
                if (lane >= o) xx += y;
            }
            wsum[lane] = xx;
            if (lane == 31) s_cnt = (int)xx;
        }
        __syncthreads();
        unsigned te = ((wid > 0) ? wsum[wid - 1] : 0u) + (x - tsum);
        hist[tid * 4 + 0] = te;                  starts[tid * 4 + 0] = te;
        hist[tid * 4 + 1] = te + h0;             starts[tid * 4 + 1] = te + h0;
        hist[tid * 4 + 2] = te + h0 + h1;        starts[tid * 4 + 2] = te + h0 + h1;
        hist[tid * 4 + 3] = te + h0 + h1 + h2;   starts[tid * 4 + 3] = te + h0 + h1 + h2;
    }
    __syncthreads();
    const int cnt = s_cnt;

    for (int i = tid; i < N_ANCH; i += BT) {
        float s = col[i];
        if (s > SCORE_THR_F) {
            int b = min((int)__fmul_rn(s, 4096.0f), NBUCK - 1);
            unsigned pos = atomicAdd(&hist[NBUCK - 1 - b], 1u);
            keys[pos] = ((unsigned long long)__float_as_uint(s) << 32) |
                        (unsigned long long)(0xFFFFFFFFu - (unsigned)i);
        }
    }
    __syncthreads();

    for (int b = tid; b < NBUCK; b += BT) {
        int s0 = (int)starts[b], e0 = (int)hist[b];
        for (int i = s0 + 1; i < e0; ++i) {
            unsigned long long kv = keys[i];
            int j = i - 1;
            while (j >= s0 && keys[j] < kv) { keys[j + 1] = keys[j]; --j; }
            keys[j + 1] = kv;
        }
    }
    __syncthreads();

    if (tid == 0) g_cnt[c] = cnt;
    for (int p = tid; p < cnt; p += BT)
        g_list[c * KEYCAP + p] = 0xFFFFFFFFu - (unsigned)keys[p];
}

// ---------------------------------------------------------------------------
// Kernel B2: greedy scan — VERBATIM R5/R9 champion (depth-32, 256 threads).
// ---------------------------------------------------------------------------
__global__ void __launch_bounds__(SCAN_T, 1)
nms_scan_kernel() {
    __shared__ unsigned slist[KEYCAP];          // 20480 B
    __shared__ unsigned srow[32][WSTRIDE];      // 20480 B
    __shared__ unsigned supp[WSTRIDE];
    __shared__ unsigned keptb[WSTRIDE];
    __shared__ unsigned s_m[8];
    __shared__ unsigned sbits[32];
    __shared__ unsigned s_kb;

    const int c = blockIdx.x;
    const int tid = threadIdx.x;
    const int lane = tid & 31;
    const int w = tid >> 5;
    const int cnt = g_cnt[c];

    for (int i = tid; i < WSTRIDE; i += SCAN_T) { supp[i] = 0u; keptb[i] = 0u; }
    for (int i = tid; i < cnt; i += SCAN_T) slist[i] = __ldg(&g_list[c * KEYCAP + i]);
    __syncthreads();

    int count = 0;
    int cur = 0;
    while (cur < cnt && count < MAXB) {
        // 1) alive check for 256 positions
        int pos = cur + tid;
        bool ok = (pos < cnt);
        unsigned ca = ok ? slist[pos] : 0u;
        bool alive = ok && !((supp[ca >> 5] >> (ca & 31)) & 1u);
        unsigned bm = __ballot_sync(0xffffffffu, alive);
        if (lane == 0) s_m[w] = bm;
        __syncthreads();

        unsigned mwords[8];
        int tot = 0;
#pragma unroll
        for (int q = 0; q < 8; ++q) { mwords[q] = s_m[q]; tot += __popc(mwords[q]); }
        int nf = min(tot, 32);

        if (nf == 0) { cur += SCAN_T; __syncthreads(); continue; }

        // 2) per-lane rank-select: psel = position (in [0,256)) of lane-th alive
        int rem = lane;
        int psel = -1;
#pragma unroll
        for (int q = 0; q < 8; ++q) {
            int cq = __popc(mwords[q]);
            if (psel < 0) {
                if (rem < cq) psel = (q << 5) + (int)__fns(mwords[q], 0, rem + 1);
                else rem -= cq;
            }
        }
        unsigned a_l = (lane < nf) ? slist[cur + psel] : 0u;

        // 3) row loads: warp w loads rows k = 4w..4w+3
        unsigned r[4][5];
#pragma unroll
        for (int j = 0; j < 4; ++j) {
            int k = (w << 2) + j;
            unsigned ak = __shfl_sync(0xffffffffu, a_l, k);
            if (k < nf) {
#pragma unroll
                for (int u = 0; u < 5; ++u) {
                    int wd = lane + (u << 5);
                    unsigned v = (wd < WORDS) ? __ldg(&g_mask[ak * WSTRIDE + wd]) : 0u;
                    r[j][u] = v;
                    srow[k][wd] = v;
                }
            } else {
#pragma unroll
                for (int u = 0; u < 5; ++u) r[j][u] = 0u;
            }
        }
        __syncthreads();

        // 4) pairwise gather + serial greedy resolve (warp 0)
        if (w == 0) {
            unsigned bitsk = 0u;
            if (lane < nf) {
                unsigned aw = a_l >> 5, ab = a_l & 31u;
#pragma unroll
                for (int m = 0; m < 32; ++m)
                    bitsk |= ((srow[m][aw] >> ab) & 1u) << m;
            }
            sbits[lane] = bitsk;
            __syncwarp(0xffffffffu);
            if (lane == 0) {
                unsigned kb = 0u;
                int cl = count;
                for (int k = 0; k < nf; ++k) {
                    unsigned bk = sbits[k];
                    if (!(bk & kb) && cl < MAXB) { kb |= (1u << k); ++cl; }
                }
                s_kb = kb;
            }
            __syncwarp(0xffffffffu);
            unsigned kb0 = s_kb;
            if (lane < nf && ((kb0 >> lane) & 1u))
                atomicOr(&keptb[a_l >> 5], 1u << (a_l & 31u));
        }
        __syncthreads();

        unsigned kb = s_kb;
        count += __popc(kb);

        // 5) OR kept rows into supp (all 8 warps, from registers)
        unsigned comb[5] = {0u, 0u, 0u, 0u, 0u};
#pragma unroll
        for (int j = 0; j < 4; ++j) {
            int k = (w << 2) + j;
            if (k < nf && ((kb >> k) & 1u)) {
#pragma unroll
                for (int u = 0; u < 5; ++u) comb[u] |= r[j][u];
            }
        }
#pragma unroll
        for (int u = 0; u < 5; ++u) {
            int wd = lane + (u << 5);
            if (wd < WORDS && comb[u]) atomicOr(&supp[wd], comb[u]);
        }
        __syncthreads();

        // 6) advance past the last selected candidate
        int plast = __shfl_sync(0xffffffffu, psel, nf - 1);
        cur += plast + 1;
    }
    __syncthreads();

    for (int i = tid; i < WSTRIDE; i += SCAN_T)
        g_kept[c * WSTRIDE + i] = keptb[i];
}

// ---------------------------------------------------------------------------
// Kernel C: assemble, one block per 32-anchor group (one g_kept word index),
// 672 threads = 32 anchors x 21 float4. g_kept words staged in smem once.
// ---------------------------------------------------------------------------
#define ASM_T 672

__global__ void __launch_bounds__(ASM_T)
assemble32_kernel(const float4* __restrict__ boxes4,
                  const float4* __restrict__ cls4,
                  float4* __restrict__ out4) {
    __shared__ unsigned sk[N_CLS];

    const int i0 = blockIdx.x << 5;            // 32-anchor group base
    const int tid = threadIdx.x;
    const unsigned wi = (unsigned)i0 >> 5;

    if (tid < N_CLS) sk[tid] = g_kept[tid * WSTRIDE + wi];
    __syncthreads();

    int a = tid / 21;
    int q = tid - a * 21;
    int i = i0 + a;
    if (i >= N_ANCH) return;

    float4 v;
    if (q == 0) {
        v = __ldg(&boxes4[i]);
    } else {
        int c0 = (q - 1) * 4;
        v = __ldg(&cls4[(i * N_CLS + c0) >> 2]);
        unsigned bi = (unsigned)i & 31u;
        if (!((sk[c0 + 0] >> bi) & 1u)) v.x = 0.0f;
        if (!((sk[c0 + 1] >> bi) & 1u)) v.y = 0.0f;
        if (!((sk[c0 + 2] >> bi) & 1u)) v.z = 0.0f;
        if (!((sk[c0 + 3] >> bi) & 1u)) v.w = 0.0f;
    }
    out4[i * 21 + q] = v;
}

// ---------------------------------------------------------------------------
extern "C" void kernel_launch(void* const* d_in, const int* in_sizes, int n_in,
                              void* d_out, int out_size) {
    const float* boxes = (const float*)d_in[0];
    const float* cls   = (const float*)d_in[1];
    float* out = (float*)d_out;

    {   // P: fused IoU tiles + transpose
        prep_kernel<<<A_BLOCKS + T_BLOCKS, 256>>>((const float4*)boxes, cls);
    }
    {   // B1: per-class sort
        size_t smem = (size_t)KEYCAP * 8 + (size_t)NBUCK * 4 * 2;
        cudaFuncSetAttribute(sort_class_kernel,
                             cudaFuncAttributeMaxDynamicSharedMemorySize,
                             (int)smem);
        sort_class_kernel<<<N_CLS, BT, smem>>>();
    }
    {   // B2: greedy scan (champion)
        nms_scan_kernel<<<N_CLS, SCAN_T>>>();
    }
    {   // C: smem-staged assemble, one block per 32 anchors
        int blocks = (N_ANCH + 31) / 32;       // 157
        assemble32_kernel<<<blocks, ASM_T>>>(
            (const float4*)boxes, (const float4*)cls, (float4*)out);
    }
}